// round 7
// baseline (speedup 1.0000x reference)
#include <cuda_runtime.h>

// DistMult edge scoring, R7: counting-sort by relation, then score.
//   out[e] = sigmoid( sum_d h[src[e]][d] * W[rel[e]][d] * h[dst[e]][d] )
//
// R6 post-mortem: L1-wavefront-bound, ~17.9 wf-cyc/edge, of which W gathers
// are 4. Sorting edges by rel (6 bins) makes r uniform along the array:
//   - W lives in 8 regs per lane, reloaded only when r changes (~6x/warp total)
//   - rel derived from position vs bin bounds (ALU, no load)
//   - {src,dst,orig} packed in one int4 -> 1 broadcast wf per pair
// Pre-pass: zero -> histogram -> scan -> scatter (block-aggregated atomics).
// Output written to out[orig]: permutation-invariant, deterministic.

#define WPB 8
#define TPB (WPB * 32)
#define GRID_BLOCKS (148 * 8)
#define PRE_TPB 256
#define MAX_E 1600000

__device__ int4 g_packed[MAX_E];   // {src, dst, orig, 0} sorted by rel (24 MB)
__device__ int  g_hist[6];
__device__ int  g_base[7];
__device__ int  g_cursor[6];

// ---------------- pre-pass ----------------

__global__ void k_zero()
{
    int t = threadIdx.x;
    if (t < 6) { g_hist[t] = 0; g_cursor[t] = 0; }
}

__global__ void k_hist(const int* __restrict__ rel, int E)
{
    __shared__ int sh[6];
    int t = threadIdx.x;
    if (t < 6) sh[t] = 0;
    __syncthreads();
    for (int e = blockIdx.x * PRE_TPB + t; e < E; e += gridDim.x * PRE_TPB)
        atomicAdd(&sh[rel[e]], 1);
    __syncthreads();
    if (t < 6) atomicAdd(&g_hist[t], sh[t]);
}

__global__ void k_scan()
{
    int acc = 0;
    for (int r = 0; r < 6; r++) {
        g_base[r] = acc;
        g_cursor[r] = acc;
        acc += g_hist[r];
    }
    g_base[6] = acc;
}

__global__ void k_scatter(const int* __restrict__ src,
                          const int* __restrict__ dst,
                          const int* __restrict__ rel, int E)
{
    __shared__ int s_cnt[6], s_base[6], s_take[6];
    int t = threadIdx.x;
    int nchunks = (E + PRE_TPB - 1) / PRE_TPB;
    for (int c = blockIdx.x; c < nchunks; c += gridDim.x) {
        int e = c * PRE_TPB + t;
        bool valid = e < E;
        int r = valid ? rel[e] : 0;
        if (t < 6) { s_cnt[t] = 0; s_take[t] = 0; }
        __syncthreads();
        if (valid) atomicAdd(&s_cnt[r], 1);
        __syncthreads();
        if (t < 6 && s_cnt[t] > 0)
            s_base[t] = atomicAdd(&g_cursor[t], s_cnt[t]);
        __syncthreads();
        if (valid) {
            int off = atomicAdd(&s_take[r], 1);
            int pos = s_base[r] + off;
            g_packed[pos] = make_int4(src[e], dst[e], e, 0);
        }
        __syncthreads();
    }
}

// ---------------- main scoring kernel ----------------

__global__ __launch_bounds__(TPB)
void distmult_main(const float* __restrict__ h,
                   const float* __restrict__ W,
                   float* __restrict__ out, int E)
{
    const int lane = threadIdx.x & 31;
    const int sub  = lane & 15;
    const int half = lane >> 4;

    const float4* __restrict__ h4 = reinterpret_cast<const float4*>(h);
    const float4* __restrict__ W4 = reinterpret_cast<const float4*>(W);

    const int b1 = g_base[1], b2 = g_base[2], b3 = g_base[3],
              b4 = g_base[4], b5 = g_base[5];

    float4 wl = make_float4(0.f, 0.f, 0.f, 0.f);
    float4 wh = wl;
    int rc = -1;   // cached relation id for (wl, wh)

    const int warp_glb  = blockIdx.x * WPB + (threadIdx.x >> 5);
    const int warp_step = gridDim.x * WPB;
    const int npairs    = (E + 1) >> 1;

    for (int p = warp_glb; p < npairs; p += warp_step) {
        int pos  = 2 * p + half;
        int posc = pos < E ? pos : E - 1;       // odd-E tail clamp

        int4 pk = g_packed[posc];               // {src, dst, orig}

        // relation from sorted position (uniform within each half-warp)
        int r = (posc >= b1) + (posc >= b2) + (posc >= b3)
              + (posc >= b4) + (posc >= b5);
        if (r != rc) {                           // rare: ~bin-crossings only
            wl = __ldg(W4 + r * 32 + sub);
            wh = __ldg(W4 + r * 32 + 16 + sub);
            rc = r;
        }

        const float4* __restrict__ up = h4 + pk.x * 32;
        const float4* __restrict__ vp = h4 + pk.y * 32;
        float4 u0 = __ldg(up + sub);
        float4 u1 = __ldg(up + 16 + sub);
        float4 v0 = __ldg(vp + sub);
        float4 v1 = __ldg(vp + 16 + sub);

        float sum = u0.x * wl.x * v0.x
                  + u0.y * wl.y * v0.y
                  + u0.z * wl.z * v0.z
                  + u0.w * wl.w * v0.w
                  + u1.x * wh.x * v1.x
                  + u1.y * wh.y * v1.y
                  + u1.z * wh.z * v1.z
                  + u1.w * wh.w * v1.w;

        #pragma unroll
        for (int off = 8; off > 0; off >>= 1)
            sum += __shfl_xor_sync(0xffffffffu, sum, off);

        if (sub == 0 && pos < E)
            out[pk.z] = 1.0f / (1.0f + __expf(-sum));
    }
}

// ---------------- fallback (unsorted, R6 shape) for E > MAX_E ----------------

__global__ __launch_bounds__(TPB)
void distmult_fallback(const float* __restrict__ h,
                       const float* __restrict__ W,
                       const int* __restrict__ src,
                       const int* __restrict__ dst,
                       const int* __restrict__ rel,
                       float* __restrict__ out, int E)
{
    const int lane = threadIdx.x & 31;
    const int sub  = lane & 15;
    const int half = lane >> 4;
    const float4* __restrict__ h4 = reinterpret_cast<const float4*>(h);
    const float4* __restrict__ W4 = reinterpret_cast<const float4*>(W);

    const int warp_glb  = blockIdx.x * WPB + (threadIdx.x >> 5);
    const int warp_step = gridDim.x * WPB;
    const int npairs    = (E + 1) >> 1;

    for (int p = warp_glb; p < npairs; p += warp_step) {
        int pos  = 2 * p + half;
        int e    = pos < E ? pos : E - 1;
        int s = __ldg(src + e);
        int d = __ldg(dst + e);
        int r = __ldg(rel + e);
        const float4* __restrict__ up = h4 + s * 32;
        const float4* __restrict__ vp = h4 + d * 32;
        const float4* __restrict__ wp = W4 + r * 32;
        float4 u0 = __ldg(up + sub), u1 = __ldg(up + 16 + sub);
        float4 v0 = __ldg(vp + sub), v1 = __ldg(vp + 16 + sub);
        float4 wl = __ldg(wp + sub), wh = __ldg(wp + 16 + sub);
        float sum = u0.x*wl.x*v0.x + u0.y*wl.y*v0.y + u0.z*wl.z*v0.z + u0.w*wl.w*v0.w
                  + u1.x*wh.x*v1.x + u1.y*wh.y*v1.y + u1.z*wh.z*v1.z + u1.w*wh.w*v1.w;
        #pragma unroll
        for (int off = 8; off > 0; off >>= 1)
            sum += __shfl_xor_sync(0xffffffffu, sum, off);
        if (sub == 0 && pos < E)
            out[e] = 1.0f / (1.0f + __expf(-sum));
    }
}

extern "C" void kernel_launch(void* const* d_in, const int* in_sizes, int n_in,
                              void* d_out, int out_size)
{
    const float* h   = (const float*)d_in[0];
    const float* W   = (const float*)d_in[1];
    const int*   src = (const int*)d_in[2];
    const int*   dst = (const int*)d_in[3];
    const int*   rel = (const int*)d_in[4];
    float* out = (float*)d_out;

    int E = in_sizes[2];
    if (E <= 0) return;

    int npairs = (E + 1) >> 1;
    int blocks = (npairs + WPB - 1) / WPB;
    if (blocks > GRID_BLOCKS) blocks = GRID_BLOCKS;
    if (blocks < 1) blocks = 1;

    if (E > MAX_E) {
        distmult_fallback<<<blocks, TPB>>>(h, W, src, dst, rel, out, E);
        return;
    }

    int pre_blocks = (E + PRE_TPB - 1) / PRE_TPB;
    if (pre_blocks > 2048) pre_blocks = 2048;

    k_zero<<<1, 32>>>();
    k_hist<<<pre_blocks, PRE_TPB>>>(rel, E);
    k_scan<<<1, 1>>>();
    k_scatter<<<pre_blocks, PRE_TPB>>>(src, dst, rel, E);
    distmult_main<<<blocks, TPB>>>(h, W, out, E);
}

// round 8
// speedup vs baseline: 2.1493x; 2.1493x over previous
#include <cuda_runtime.h>

// DistMult edge scoring, R8: R6 scheme widened to 4 edges/warp.
//   out[e] = sigmoid( sum_d h[src[e]][d] * W[rel[e]][d] * h[dst[e]][d] )
// h: [100000,128] f32 (L2-resident), W: [6,128] f32 (L1-resident), idx int32.
//
// 4 edges per warp, 8 lanes per edge. Each lane covers float4 positions
// sub8 + 8j (j=0..3) of its row -> every LDG.128 is 4 rows x 128B = fully
// coalesced. Dot product done in two phases (j={0,1}, then j={2,3}) to keep
// live registers ~6 float4 instead of 12 (R5 occupancy lesson).
// wf/edge ~= 8 (u,v) + <=4 (W, L1-hit) + 0.75 (idx) + 0.75 (shfl) + 0.25 (stg).

#define WPB 4
#define TPB (WPB * 32)
#define GRID_BLOCKS (148 * 12)

__global__ __launch_bounds__(TPB)
void distmult_kernel(const float* __restrict__ h,
                     const float* __restrict__ W,
                     const int* __restrict__ src,
                     const int* __restrict__ dst,
                     const int* __restrict__ rel,
                     float* __restrict__ out,
                     int E)
{
    const int lane = threadIdx.x & 31;
    const int sub  = lane & 7;    // lane within 8-lane edge group
    const int grp  = lane >> 3;   // which of 4 edges

    const float4* __restrict__ h4 = reinterpret_cast<const float4*>(h);
    const float4* __restrict__ W4 = reinterpret_cast<const float4*>(W);

    const int warp_glb  = blockIdx.x * WPB + (threadIdx.x >> 5);
    const int warp_step = gridDim.x * WPB;
    const int nquads    = (E + 3) >> 2;

    for (int q = warp_glb; q < nquads; q += warp_step) {
        int e  = 4 * q + grp;
        int ec = e < E ? e : E - 1;            // tail clamp (dup compute ok)

        int s = __ldg(src + ec);
        int d = __ldg(dst + ec);
        int r = __ldg(rel + ec);

        const float4* __restrict__ up = h4 + s * 32 + sub;
        const float4* __restrict__ vp = h4 + d * 32 + sub;
        const float4* __restrict__ wp = W4 + r * 32 + sub;

        // Phase 1: float4 positions sub, sub+8
        float4 u0 = __ldg(up);
        float4 u1 = __ldg(up + 8);
        float4 v0 = __ldg(vp);
        float4 v1 = __ldg(vp + 8);
        float4 w0 = __ldg(wp);
        float4 w1 = __ldg(wp + 8);

        float sum = u0.x * w0.x * v0.x
                  + u0.y * w0.y * v0.y
                  + u0.z * w0.z * v0.z
                  + u0.w * w0.w * v0.w
                  + u1.x * w1.x * v1.x
                  + u1.y * w1.y * v1.y
                  + u1.z * w1.z * v1.z
                  + u1.w * w1.w * v1.w;

        // Phase 2: float4 positions sub+16, sub+24
        u0 = __ldg(up + 16);
        u1 = __ldg(up + 24);
        v0 = __ldg(vp + 16);
        v1 = __ldg(vp + 24);
        w0 = __ldg(wp + 16);
        w1 = __ldg(wp + 24);

        sum += u0.x * w0.x * v0.x
             + u0.y * w0.y * v0.y
             + u0.z * w0.z * v0.z
             + u0.w * w0.w * v0.w
             + u1.x * w1.x * v1.x
             + u1.y * w1.y * v1.y
             + u1.z * w1.z * v1.z
             + u1.w * w1.w * v1.w;

        // 8-lane reduction (xor 4,2,1 stays within each group)
        #pragma unroll
        for (int off = 4; off > 0; off >>= 1)
            sum += __shfl_xor_sync(0xffffffffu, sum, off);

        if (sub == 0 && e < E)
            out[e] = 1.0f / (1.0f + __expf(-sum));
    }
}

extern "C" void kernel_launch(void* const* d_in, const int* in_sizes, int n_in,
                              void* d_out, int out_size)
{
    const float* h   = (const float*)d_in[0];
    const float* W   = (const float*)d_in[1];
    const int*   src = (const int*)d_in[2];
    const int*   dst = (const int*)d_in[3];
    const int*   rel = (const int*)d_in[4];
    float* out = (float*)d_out;

    int E = in_sizes[2];
    if (E <= 0) return;

    int nquads = (E + 3) >> 2;
    int blocks_needed = (nquads + WPB - 1) / WPB;
    if (blocks_needed < 1) blocks_needed = 1;
    int blocks = blocks_needed < GRID_BLOCKS ? blocks_needed : GRID_BLOCKS;
    distmult_kernel<<<blocks, TPB>>>(h, W, src, dst, rel, out, E);
}